// round 8
// baseline (speedup 1.0000x reference)
#include <cuda_runtime.h>
#include <cuda_bf16.h>

#define HH 512
#define WW 1024
#define EPSV 1e-5f
#define BPB 64            // reduction blocks per batch
#define RED_THREADS 256
#define VPB ((HH * WW / 4) / BPB)   // float4 vectors per reduction block = 2048

// Scratch (no allocations allowed) — sized for up to 128 batches.
__device__ float g_es [128 * BPB];
__device__ float g_esr[128 * BPB];
__device__ int   g_nvis[128];
__device__ float g_sr  [128];

// ---------------------------------------------------------------------------
// K0: zero the entire output buffer (svf region must start at 0; pts/loss get
// overwritten later). Also zero the per-batch scatter accumulators.
// ---------------------------------------------------------------------------
__global__ void k_zero(float* __restrict__ out, long n4, long n) {
    long i = (long)blockIdx.x * blockDim.x + threadIdx.x;
    float4* o4 = (float4*)out;
    const float4 z = make_float4(0.f, 0.f, 0.f, 0.f);
    long stride = (long)gridDim.x * blockDim.x;
    for (long v = i; v < n4; v += stride) o4[v] = z;
    long tail0 = n4 * 4;
    if (i < n - tail0) out[tail0 + i] = 0.f;
    if (blockIdx.x == 0 && threadIdx.x < 128) {
        g_nvis[threadIdx.x] = 0;
        g_sr[threadIdx.x]   = 0.f;
    }
}

// ---------------------------------------------------------------------------
// K1: per-batch partial reductions of exp_svf and exp_svf*reward.
// grid = (BPB, B). Pure float4 reads, fully coalesced.
// ---------------------------------------------------------------------------
__global__ void k_reduce(const float4* __restrict__ e4,
                         const float4* __restrict__ r4) {
    int b   = blockIdx.y;
    int blk = blockIdx.x;
    long base = (long)b * (HH * WW / 4) + (long)blk * VPB;

    float es = 0.f, esr = 0.f;
#pragma unroll
    for (int k = 0; k < VPB / RED_THREADS; k++) {
        long idx = base + (long)k * RED_THREADS + threadIdx.x;
        float4 e = e4[idx];
        float4 r = r4[idx];
        es  += (e.x + e.y) + (e.z + e.w);
        esr += e.x * r.x + e.y * r.y + e.z * r.z + e.w * r.w;
    }
#pragma unroll
    for (int off = 16; off > 0; off >>= 1) {
        es  += __shfl_down_sync(0xFFFFFFFFu, es,  off);
        esr += __shfl_down_sync(0xFFFFFFFFu, esr, off);
    }
    __shared__ float se[RED_THREADS / 32], sm[RED_THREADS / 32];
    int w = threadIdx.x >> 5;
    if ((threadIdx.x & 31) == 0) { se[w] = es; sm[w] = esr; }
    __syncthreads();
    if (threadIdx.x == 0) {
        float a = 0.f, c = 0.f;
#pragma unroll
        for (int i = 0; i < RED_THREADS / 32; i++) { a += se[i]; c += sm[i]; }
        g_es [b * BPB + blk] = a;
        g_esr[b * BPB + blk] = c;
    }
}

// ---------------------------------------------------------------------------
// Shared point-interpolation helper. Mul-then-add (no FMA) to match JAX's
// start + t*(end-start) rounding so int truncation picks the same cell.
// ---------------------------------------------------------------------------
__device__ __forceinline__ void interp_point(const float* __restrict__ gt,
                                             int b, int p, int T, int Npts,
                                             int ms, float& px, float& py) {
    if (p == Npts - 1) {
        const float* g = gt + ((long)b * T + (T - 1)) * 9;
        px = g[2] * 0.5f;
        py = g[5] * 0.5f;
    } else {
        int s = p / ms;
        int j = p - s * ms;
        const float* g = gt + ((long)b * T + s) * 9;
        float sx = g[2]  * 0.5f, sy = g[5]  * 0.5f;
        float ex = g[11] * 0.5f, ey = g[14] * 0.5f;
        float t = (ms > 1) ? (float)j / (float)(ms - 1) : 0.f;
        px = __fadd_rn(sx, __fmul_rn(t, __fsub_rn(ex, sx)));
        py = __fadd_rn(sy, __fmul_rn(t, __fsub_rn(ey, sy)));
    }
}

__device__ __forceinline__ long point_cell(int b, float px, float py) {
    int xi = (int)fminf(fmaxf(px, 0.f), (float)(HH - 1));
    int yi = (int)fminf(fmaxf(py, 0.f), (float)(WW - 1));
    return (long)b * (HH * WW) + (long)xi * WW + yi;
}

// ---------------------------------------------------------------------------
// K2: one thread per interpolated point. Writes interp_pts output, scatters
// visitation (dedup via atomicExch), accumulates per-batch nvis and
// sum(reward @ visited cells).
// ---------------------------------------------------------------------------
__global__ void k_points(const float* __restrict__ gt,
                         const float* __restrict__ rew,
                         float* __restrict__ svf,
                         float* __restrict__ pts_out,
                         int B, int T, int Npts, int ms) {
    int idx = blockIdx.x * blockDim.x + threadIdx.x;
    if (idx >= B * Npts) return;
    int b = idx / Npts;
    int p = idx - b * Npts;

    float px, py;
    interp_point(gt, b, p, T, Npts, ms, px, py);

    pts_out[(long)idx * 2]     = px;
    pts_out[(long)idx * 2 + 1] = py;

    long cell = point_cell(b, px, py);
    float old = atomicExch(&svf[cell], 1.0f);
    if (old == 0.0f) {
        atomicAdd(&g_nvis[b], 1);
        atomicAdd(&g_sr[b], rew[cell]);
    }
}

// ---------------------------------------------------------------------------
// K3: overwrite each visited cell with its normalized value 1/(nvis+eps).
// Idempotent stores; every visited cell is the image of >=1 point.
// ---------------------------------------------------------------------------
__global__ void k_scale(const float* __restrict__ gt,
                        float* __restrict__ svf,
                        int B, int T, int Npts, int ms) {
    int idx = blockIdx.x * blockDim.x + threadIdx.x;
    if (idx >= B * Npts) return;
    int b = idx / Npts;
    int p = idx - b * Npts;

    float px, py;
    interp_point(gt, b, p, T, Npts, ms, px, py);
    long cell = point_cell(b, px, py);
    svf[cell] = 1.0f / ((float)g_nvis[b] + EPSV);
}

// ---------------------------------------------------------------------------
// K4: final deterministic reduction -> scalar loss.
// loss = mean_b( esr_b/(es_b+eps) ) - mean_b( sr_b/(nvis_b+eps) )
// ---------------------------------------------------------------------------
__global__ void k_final(float* __restrict__ out_loss, int B) {
    int b = threadIdx.x;
    float et = 0.f, st = 0.f;
    if (b < B) {
        float es = 0.f, esr = 0.f;
#pragma unroll 8
        for (int i = 0; i < BPB; i++) {
            es  += g_es [b * BPB + i];
            esr += g_esr[b * BPB + i];
        }
        et = esr / (es + EPSV);
        st = g_sr[b] / ((float)g_nvis[b] + EPSV);
    }
    __shared__ float se[128], ss[128];
    se[threadIdx.x] = et;
    ss[threadIdx.x] = st;
    __syncthreads();
#pragma unroll
    for (int off = 64; off > 0; off >>= 1) {
        if (threadIdx.x < off) {
            se[threadIdx.x] += se[threadIdx.x + off];
            ss[threadIdx.x] += ss[threadIdx.x + off];
        }
        __syncthreads();
    }
    if (threadIdx.x == 0)
        out_loss[0] = (se[0] - ss[0]) / (float)B;
}

// ---------------------------------------------------------------------------
extern "C" void kernel_launch(void* const* d_in, const int* in_sizes, int n_in,
                              void* d_out, int out_size) {
    const float* gt      = (const float*)d_in[0];  // (B,T,3,3)
    const float* exp_svf = (const float*)d_in[1];  // (B,H,W)
    const float* rew     = (const float*)d_in[2];  // (B,H,W)
    float* out = (float*)d_out;

    int B = in_sizes[1] / (HH * WW);
    int T = in_sizes[0] / (B * 9);
    long grid_elems = (long)B * HH * WW;
    // out layout: [loss(1)][svf(B*H*W)][interp_pts(B*Npts*2)]
    int Npts = (int)(((long)out_size - 1 - grid_elems) / (2L * B));
    int ms = (T > 1 && Npts > 1) ? (Npts - 1) / (T - 1) : 1;
    if (ms < 1) ms = 1;

    float* svf = out + 1;
    float* pts = out + 1 + grid_elems;

    long n  = (long)out_size;
    long n4 = n / 4;  // out base is 256B-aligned -> float4 OK

    k_zero<<<4096, 256>>>(out, n4, n);

    dim3 rg(BPB, B);
    k_reduce<<<rg, RED_THREADS>>>((const float4*)exp_svf, (const float4*)rew);

    int tot = B * Npts;
    int pblocks = (tot + 255) / 256;
    k_points<<<pblocks, 256>>>(gt, rew, svf, pts, B, T, Npts, ms);
    k_scale<<<pblocks, 256>>>(gt, svf, B, T, Npts, ms);
    k_final<<<1, 128>>>(out, B);
}